// round 1
// baseline (speedup 1.0000x reference)
#include <cuda_runtime.h>
#include <cuda_bf16.h>
#include <cstdint>

// HashEmbedding: out[row, :] = embedding[hashed_ids[row], :]
// rows = 8*4096 = 32768, D = 1024 fp32 (= 256 float4 per row).
// Pure bandwidth kernel: 134 MB store + gather reads (table fits in L2).
//
// Layout: one block per output row, 128 threads, each thread copies
// 2 float4 (stride-128 within the row) -> fully coalesced 16B accesses.

static constexpr int D_F4 = 256;       // 1024 floats / 4 per float4
static constexpr int THREADS = 128;    // 2 float4 per thread

__global__ void __launch_bounds__(THREADS)
hash_embedding_gather(const int* __restrict__ hashed_ids,
                      const float4* __restrict__ emb,
                      float4* __restrict__ out,
                      int nrows)
{
    int row = blockIdx.x;
    if (row >= nrows) return;

    int id = __ldg(hashed_ids + row);

    const float4* __restrict__ src = emb + (size_t)id  * D_F4;
    float4* __restrict__       dst = out + (size_t)row * D_F4;

    int t = threadIdx.x;
    // Two independent 16B loads issued back-to-back (MLP=2 per thread).
    float4 v0 = __ldg(src + t);
    float4 v1 = __ldg(src + t + THREADS);
    dst[t]           = v0;
    dst[t + THREADS] = v1;
}

extern "C" void kernel_launch(void* const* d_in, const int* in_sizes, int n_in,
                              void* d_out, int out_size)
{
    // metadata order: input_ids (unused), hashed_ids (int32), embedding (fp32)
    const int*    hashed_ids = (const int*)d_in[1];
    const float4* emb        = (const float4*)d_in[2];
    float4*       out        = (float4*)d_out;

    int nrows = in_sizes[1];   // 32768

    hash_embedding_gather<<<nrows, THREADS>>>(hashed_ids, emb, out, nrows);
}

// round 2
// speedup vs baseline: 1.1281x; 1.1281x over previous
#include <cuda_runtime.h>
#include <cuda_bf16.h>
#include <cstdint>

// HashEmbedding gather: out[row,:] = embedding[hashed_ids[row],:]
// rows = 32768, D = 1024 fp32 = 256 float4.
//
// R2 layout: 256-thread blocks, 4 rows per block (64 threads/row),
// 4 independent float4 loads per thread (MLP=4), streaming stores
// (__stcs) so the 134MB output stream doesn't evict the 40MB table
// from L2.

static constexpr int D_F4 = 256;          // float4 per row
static constexpr int THREADS = 256;
static constexpr int ROWS_PER_BLK = 4;    // 64 threads per row
static constexpr int LANES = 64;          // threads per row

__global__ void __launch_bounds__(THREADS)
hash_embedding_gather(const int* __restrict__ hashed_ids,
                      const float4* __restrict__ emb,
                      float4* __restrict__ out,
                      int nrows)
{
    int t    = threadIdx.x;
    int sub  = t >> 6;        // which row within the block (0..3)
    int lane = t & 63;        // position within the row (0..63)

    int row = blockIdx.x * ROWS_PER_BLK + sub;
    if (row >= nrows) return;

    int id = __ldg(hashed_ids + row);

    const float4* __restrict__ src = emb + (size_t)id  * D_F4;
    float4*       __restrict__ dst = out + (size_t)row * D_F4;

    // 4 independent 16B loads, front-batched (MLP=4 per thread).
    float4 v0 = __ldg(src + lane);
    float4 v1 = __ldg(src + lane + LANES);
    float4 v2 = __ldg(src + lane + 2 * LANES);
    float4 v3 = __ldg(src + lane + 3 * LANES);

    // Streaming stores: output is write-once, keep the table in L2.
    __stcs(dst + lane,             v0);
    __stcs(dst + lane + LANES,     v1);
    __stcs(dst + lane + 2 * LANES, v2);
    __stcs(dst + lane + 3 * LANES, v3);
}

extern "C" void kernel_launch(void* const* d_in, const int* in_sizes, int n_in,
                              void* d_out, int out_size)
{
    // metadata order: input_ids (unused), hashed_ids (int32), embedding (fp32)
    const int*    hashed_ids = (const int*)d_in[1];
    const float4* emb        = (const float4*)d_in[2];
    float4*       out        = (float4*)d_out;

    int nrows = in_sizes[1];   // 32768
    int blocks = (nrows + ROWS_PER_BLK - 1) / ROWS_PER_BLK;

    hash_embedding_gather<<<blocks, THREADS>>>(hashed_ids, emb, out, nrows);
}